// round 6
// baseline (speedup 1.0000x reference)
#include <cuda_runtime.h>

// Fixed problem shapes (QGenBelief reference)
#define B   64
#define Q   16
#define O   20
#define D   256
#define T   4096
#define D4  (D / 4)          // 64 float4 lanes per row
#define RPB 64               // t-rows per scatter block
#define RPT 16               // t-rows per thread (RPB / 4 row-groups)

// Scratch: belief table [B, Q, D] f32 = 1 MB
__device__ float g_belief[B * Q * D];

__device__ __forceinline__ float fast_tanh(float x) {
    float y;
    asm("tanh.approx.f32 %0, %1;" : "=f"(y) : "f"(x));
    return y;
}

// ---------------------------------------------------------------------------
// Kernel 1: belief[b,q,:] = tanh( softmax(logits[b,q,:]) @ emb[cat[b,:], :] )
// One block per (b,q); 256 threads (one per d). Emb table is L2-resident.
// ---------------------------------------------------------------------------
__global__ __launch_bounds__(D) void belief_kernel(
    const float* __restrict__ logits,      // [B,Q,O]
    const float* __restrict__ emb,         // [NUM_CAT, D]
    const int*   __restrict__ cats)        // [B,O]
{
    const int bq = blockIdx.x;             // 0 .. B*Q-1
    const int b  = bq / Q;
    const int tid = threadIdx.x;

    __shared__ float s_p[O];
    __shared__ int   s_cat[O];

    if (tid < O) {
        s_p[tid]   = logits[bq * O + tid];
        s_cat[tid] = cats[b * O + tid];
    }
    __syncthreads();

    if (tid == 0) {
        float m = s_p[0];
        #pragma unroll
        for (int o = 1; o < O; ++o) m = fmaxf(m, s_p[o]);
        float s = 0.f;
        #pragma unroll
        for (int o = 0; o < O; ++o) { float e = __expf(s_p[o] - m); s_p[o] = e; s += e; }
        float inv = 1.f / s;
        #pragma unroll
        for (int o = 0; o < O; ++o) s_p[o] *= inv;
    }
    __syncthreads();

    float acc = 0.f;
    #pragma unroll
    for (int o = 0; o < O; ++o)
        acc = fmaf(s_p[o], emb[s_cat[o] * D + tid], acc);

    g_belief[bq * D + tid] = fast_tanh(acc);

    // Allow the dependent scatter grid to begin launching.
    cudaTriggerProgrammaticLaunchCompletion();
}

// ---------------------------------------------------------------------------
// Kernel 2: scatter. Block covers 64 consecutive t-rows of one batch.
// Prologue (boundaries, qi per row) is independent of g_belief and runs
// before the PDL grid-dependency sync; belief reads come after.
// ---------------------------------------------------------------------------
__global__ __launch_bounds__(256) void scatter_kernel(
    const int*  __restrict__ cum,     // [B,Q]
    const int*  __restrict__ nq,      // [B]
    float4*     __restrict__ out)     // [B,T,D] as float4
{
    const int b   = blockIdx.y;
    const int t0  = blockIdx.x * RPB;
    const int tid = threadIdx.x;

    __shared__ int s_bnd[Q - 1];
    __shared__ int s_nq;
    __shared__ int s_qi[RPB];

    if (tid < Q - 1) s_bnd[tid] = cum[b * Q + 1 + tid] - 1;
    if (tid == Q - 1) s_nq = nq[b];
    __syncthreads();

    if (tid < RPB) {
        const int t   = t0 + tid;
        const int nqb = s_nq;
        int qi = 0;
        #pragma unroll
        for (int j = 1; j < Q; ++j)
            if (j <= nqb - 1 && t >= s_bnd[j - 1]) qi++;
        s_qi[tid] = (qi < nqb - 1) ? qi : -1;   // -1 => zeros
    }
    __syncthreads();

    const int g  = tid >> 6;          // row-group 0..3
    const int d4 = tid & 63;          // float4 lane

    const float4* bel = reinterpret_cast<const float4*>(g_belief)
                        + (b * Q) * D4 + d4;
    float4* o = out + ((size_t)b * T + t0 + g * RPT) * D4 + d4;

    // Wait for belief_kernel's writes to be visible before consuming them.
    cudaGridDependencySynchronize();

    int    prev = -2;
    float4 v = make_float4(0.f, 0.f, 0.f, 0.f);

    #pragma unroll
    for (int i = 0; i < RPT; ++i) {
        const int qi = s_qi[g * RPT + i];     // warp-uniform broadcast
        if (qi != prev) {
            prev = qi;
            v = (qi >= 0) ? bel[qi * D4] : make_float4(0.f, 0.f, 0.f, 0.f);
        }
        __stcs(o + i * D4, v);                // streaming store, evict-first
    }
}

// ---------------------------------------------------------------------------
extern "C" void kernel_launch(void* const* d_in, const int* in_sizes, int n_in,
                              void* d_out, int out_size)
{
    const float* logits = (const float*)d_in[0];
    const float* emb    = (const float*)d_in[1];
    const int*   cats   = (const int*)d_in[2];
    const int*   cum    = (const int*)d_in[3];
    const int*   nq     = (const int*)d_in[4];

    belief_kernel<<<B * Q, D>>>(logits, emb, cats);

    // Scatter with programmatic dependent launch: prologue overlaps belief tail.
    cudaLaunchAttribute attr[1];
    attr[0].id = cudaLaunchAttributeProgrammaticStreamSerialization;
    attr[0].val.programmaticStreamSerializationAllowed = 1;

    cudaLaunchConfig_t cfg = {};
    cfg.gridDim  = dim3(T / RPB, B, 1);
    cfg.blockDim = dim3(256, 1, 1);
    cfg.dynamicSmemBytes = 0;
    cfg.stream   = 0;
    cfg.attrs    = attr;
    cfg.numAttrs = 1;

    cudaLaunchKernelEx(&cfg, scatter_kernel, cum, nq, (float4*)d_out);
}

// round 7
// speedup vs baseline: 1.1017x; 1.1017x over previous
#include <cuda_runtime.h>

// Fixed problem shapes (QGenBelief reference)
#define B   64
#define Q   16
#define O   20
#define D   256
#define T   4096
#define D4  (D / 4)          // 64 float4 lanes per row
#define RPB 64               // t-rows per block
#define RPT 16               // t-rows per thread (RPB / 4 row-groups)

__device__ __forceinline__ float fast_tanh(float x) {
    float y;
    asm("tanh.approx.f32 %0, %1;" : "=f"(y) : "f"(x));
    return y;
}

// ---------------------------------------------------------------------------
// Fused kernel: each block owns 64 consecutive t-rows of one batch.
// qi is monotone in t, so the block needs beliefs for a contiguous range of
// questions [qi0, qiL] (usually 1-2). Compute them in shared, then stream
// the 64 output rows with one float4 lane per thread.
// ---------------------------------------------------------------------------
__global__ __launch_bounds__(256) void fused_kernel(
    const float* __restrict__ logits,  // [B,Q,O]
    const float* __restrict__ emb,     // [NUM_CAT,D]
    const int*   __restrict__ cats,    // [B,O]
    const int*   __restrict__ cum,     // [B,Q]
    const int*   __restrict__ nq,      // [B]
    float4*      __restrict__ out)     // [B,T,D] as float4
{
    const int b   = blockIdx.y;
    const int t0  = blockIdx.x * RPB;
    const int tid = threadIdx.x;

    __shared__ int   s_bnd[Q - 1];
    __shared__ int   s_nq;
    __shared__ int   s_qi[RPB];        // raw qi per row
    __shared__ int   s_cat[O];
    __shared__ float s_p[Q * O];       // softmax probs per distinct q
    __shared__ float s_bel[Q * D];     // belief rows for the block (16 KB max)

    if (tid < Q - 1)              s_bnd[tid]      = cum[b * Q + 1 + tid] - 1;
    if (tid == Q - 1)             s_nq            = nq[b];
    if (tid >= 32 && tid < 32 + O) s_cat[tid - 32] = cats[b * O + (tid - 32)];
    __syncthreads();

    const int nqb = s_nq;

    if (tid < RPB) {
        const int t = t0 + tid;
        int qi = 0;
        #pragma unroll
        for (int j = 1; j < Q; ++j)
            if (j <= nqb - 1 && t >= s_bnd[j - 1]) qi++;
        s_qi[tid] = qi;
    }
    __syncthreads();

    const int qi0 = s_qi[0];
    const int qiL = min(s_qi[RPB - 1], nqb - 2);
    const int nd  = qiL - qi0 + 1;     // number of valid distinct questions

    if (nd > 0) {
        // Softmax for each distinct q: one thread each (20 elems, trivial).
        if (tid < nd) {
            const int q = qi0 + tid;
            float v[O];
            #pragma unroll
            for (int o = 0; o < O; ++o) v[o] = logits[(b * Q + q) * O + o];
            float m = v[0];
            #pragma unroll
            for (int o = 1; o < O; ++o) m = fmaxf(m, v[o]);
            float s = 0.f;
            #pragma unroll
            for (int o = 0; o < O; ++o) { v[o] = __expf(v[o] - m); s += v[o]; }
            const float inv = 1.f / s;
            #pragma unroll
            for (int o = 0; o < O; ++o) s_p[tid * O + o] = v[o] * inv;
        }
        __syncthreads();

        // Belief rows: single pass over emb (each value loaded once per block),
        // accumulating up to 4 questions at a time.
        for (int c0 = 0; c0 < nd; c0 += 4) {
            const int cn = min(4, nd - c0);
            float acc[4] = {0.f, 0.f, 0.f, 0.f};
            #pragma unroll
            for (int o = 0; o < O; ++o) {
                const float e = emb[s_cat[o] * D + tid];
                #pragma unroll
                for (int k = 0; k < 4; ++k)
                    if (k < cn) acc[k] = fmaf(s_p[(c0 + k) * O + o], e, acc[k]);
            }
            #pragma unroll
            for (int k = 0; k < 4; ++k)
                if (k < cn) s_bel[(c0 + k) * D + tid] = fast_tanh(acc[k]);
        }
    }
    __syncthreads();

    // Store stream: 4 row-groups x 64 float4 lanes; belief read from shared
    // only when qi changes.
    const int g  = tid >> 6;
    const int d4 = tid & 63;

    float4* o = out + ((size_t)b * T + t0 + g * RPT) * D4 + d4;

    int    prev = -2;
    float4 v = make_float4(0.f, 0.f, 0.f, 0.f);

    #pragma unroll
    for (int i = 0; i < RPT; ++i) {
        const int qraw  = s_qi[g * RPT + i];          // warp-uniform
        const int key   = (qraw < nqb - 1) ? qraw : -1;
        if (key != prev) {
            prev = key;
            v = (key >= 0)
                ? *reinterpret_cast<const float4*>(&s_bel[(key - qi0) * D + d4 * 4])
                : make_float4(0.f, 0.f, 0.f, 0.f);
        }
        __stcs(o + i * D4, v);
    }
}

// ---------------------------------------------------------------------------
extern "C" void kernel_launch(void* const* d_in, const int* in_sizes, int n_in,
                              void* d_out, int out_size)
{
    const float* logits = (const float*)d_in[0];
    const float* emb    = (const float*)d_in[1];
    const int*   cats   = (const int*)d_in[2];
    const int*   cum    = (const int*)d_in[3];
    const int*   nq     = (const int*)d_in[4];

    dim3 grid(T / RPB, B);
    fused_kernel<<<grid, 256>>>(logits, emb, cats, cum, nq, (float4*)d_out);
}